// round 2
// baseline (speedup 1.0000x reference)
#include <cuda_runtime.h>
#include <cuda_bf16.h>

// Closed-form coefficients for the two blocks (x-block, t-block):
//   A(z) = e0 + e1*z + e2*z^2 + e3*z^3 + s*(f0 + f1*z + f2*z^2),  s = sqrt(1-z^2)
// Layout (28 floats = 7 float4):
//   [0..3]   ex_r[4]   [4..7]   ex_i[4]
//   [8..10]  fx_r[3]   [11..13] fx_i[3]
//   [14..17] et_r[4]   [18..21] et_i[4]
//   [22..24] ft_r[3]   [25..27] ft_i[3]
__device__ __align__(16) float g_cf[28];

__device__ __forceinline__ float2 cmul(float2 a, float2 b) {
    return make_float2(a.x * b.x - a.y * b.y, a.x * b.y + a.y * b.x);
}

// Propagate v = RZ(p_{n-1}) S ... S RZ(p_0) (1,1)^T symbolically.
// After d S-steps, v0/v1 are homogeneous degree-d polys in (z,s);
// coeff index j = power of s (monomial z^(d-j) s^j). Returns out[j] = v0[j]+v1[j].
__device__ void chain_coeffs(const float* ph, int n, float2* out) {
    float2 v0[4], v1[4], n0[4], n1[4];
    float s, c;
    sincosf(0.5f * ph[0], &s, &c);
    v0[0] = make_float2(c, -s);
    v1[0] = make_float2(c, s);
    int deg = 0;
    for (int k = 1; k < n; k++) {
        // S(z) step: v0' = z*v0 + i*s*v1 ; v1' = i*s*v0 + z*v1
        for (int j = 0; j <= deg + 1; j++) {
            n0[j] = make_float2(0.f, 0.f);
            n1[j] = make_float2(0.f, 0.f);
        }
        for (int j = 0; j <= deg; j++) {
            // z * v : same s-power j
            n0[j].x += v0[j].x; n0[j].y += v0[j].y;
            n1[j].x += v1[j].x; n1[j].y += v1[j].y;
            // i*s * other : s-power j+1, multiply by i
            n0[j + 1].x += -v1[j].y; n0[j + 1].y += v1[j].x;
            n1[j + 1].x += -v0[j].y; n1[j + 1].y += v0[j].x;
        }
        deg++;
        // RZ(p_k): v0 *= (c - i s), v1 *= (c + i s)
        sincosf(0.5f * ph[k], &s, &c);
        float2 m0 = make_float2(c, -s), m1 = make_float2(c, s);
        for (int j = 0; j <= deg; j++) {
            v0[j] = cmul(n0[j], m0);
            v1[j] = cmul(n1[j], m1);
        }
    }
    for (int j = 0; j <= deg; j++)
        out[j] = make_float2(v0[j].x + v1[j].x, v0[j].y + v1[j].y);
}

__global__ void qpinn_setup(const float* __restrict__ ph_x1,
                            const float* __restrict__ ph_x2,
                            const float* __restrict__ ph_t1,
                            const float* __restrict__ ph_t2) {
    if (threadIdx.x != 0 || blockIdx.x != 0) return;
    const float* phs[4] = {ph_x1, ph_x2, ph_t1, ph_t2};
    const int lens[4] = {3, 4, 3, 4};

    for (int blk = 0; blk < 2; blk++) {       // 0: x-block, 1: t-block
        float2 e[4], f[3];
        for (int j = 0; j < 4; j++) e[j] = make_float2(0.f, 0.f);
        for (int j = 0; j < 3; j++) f[j] = make_float2(0.f, 0.f);

        // chain of length 3 -> degree 2: out2[j], monomial z^(2-j) s^j
        // out = (o0-o2) z^2 + o1 z s + o2
        float2 o2[3];
        chain_coeffs(phs[2 * blk], lens[2 * blk], o2);
        e[0].x += o2[2].x;           e[0].y += o2[2].y;
        e[2].x += o2[0].x - o2[2].x; e[2].y += o2[0].y - o2[2].y;
        f[1].x += o2[1].x;           f[1].y += o2[1].y;

        // chain of length 4 -> degree 3: out3[j], monomial z^(3-j) s^j
        // out = (o0-o2) z^3 + o2 z + s[(o1-o3) z^2 + o3]
        float2 o3[4];
        chain_coeffs(phs[2 * blk + 1], lens[2 * blk + 1], o3);
        e[1].x += o3[2].x;           e[1].y += o3[2].y;
        e[3].x += o3[0].x - o3[2].x; e[3].y += o3[0].y - o3[2].y;
        f[0].x += o3[3].x;           f[0].y += o3[3].y;
        f[2].x += o3[1].x - o3[3].x; f[2].y += o3[1].y - o3[3].y;

        // Fold the global 1/16 into the x-block only.
        float scale = (blk == 0) ? 0.0625f : 1.0f;
        float* base = g_cf + blk * 14;
        for (int j = 0; j < 4; j++) { base[j]     = e[j].x * scale; base[4 + j]  = e[j].y * scale; }
        for (int j = 0; j < 3; j++) { base[8 + j] = f[j].x * scale; base[11 + j] = f[j].y * scale; }
    }
}

// Evaluate one block: A = P(z) + s*Q(z), P cubic, Q quadratic (Horner).
__device__ __forceinline__ void eval_block(float z, float s, const float* cf,
                                           float& Ar, float& Ai) {
    float pr = fmaf(cf[3], z, cf[2]);
    pr = fmaf(pr, z, cf[1]);
    pr = fmaf(pr, z, cf[0]);
    float pi = fmaf(cf[7], z, cf[6]);
    pi = fmaf(pi, z, cf[5]);
    pi = fmaf(pi, z, cf[4]);
    float qr = fmaf(cf[10], z, cf[9]);
    qr = fmaf(qr, z, cf[8]);
    float qi = fmaf(cf[13], z, cf[12]);
    qi = fmaf(qi, z, cf[11]);
    Ar = fmaf(s, qr, pr);
    Ai = fmaf(s, qi, pi);
}

__device__ __forceinline__ float eval_one(float t, float x, const float* cf) {
    float sx = sqrtf(fmaxf(fmaf(-x, x, 1.0f), 0.0f));
    float st = sqrtf(fmaxf(fmaf(-t, t, 1.0f), 0.0f));
    float Axr, Axi, Atr, Ati;
    eval_block(x, sx, cf, Axr, Axi);
    eval_block(t, st, cf + 14, Atr, Ati);
    return fmaf(Axr, Atr, -Axi * Ati);
}

__global__ void __launch_bounds__(256)
qpinn_main(const float* __restrict__ t, const float* __restrict__ x,
           float* __restrict__ out, int n) {
    // Pull the 28 coefficients into registers (L1/L2-cached broadcast loads).
    float cf[28];
    const float4* g4 = reinterpret_cast<const float4*>(g_cf);
#pragma unroll
    for (int i = 0; i < 7; i++) {
        float4 v = g4[i];
        cf[4 * i] = v.x; cf[4 * i + 1] = v.y; cf[4 * i + 2] = v.z; cf[4 * i + 3] = v.w;
    }

    int n4 = n >> 2;
    int i = blockIdx.x * blockDim.x + threadIdx.x;
    if (i < n4) {
        float4 tv = reinterpret_cast<const float4*>(t)[i];
        float4 xv = reinterpret_cast<const float4*>(x)[i];
        float4 o;
        o.x = eval_one(tv.x, xv.x, cf);
        o.y = eval_one(tv.y, xv.y, cf);
        o.z = eval_one(tv.z, xv.z, cf);
        o.w = eval_one(tv.w, xv.w, cf);
        reinterpret_cast<float4*>(out)[i] = o;
    }
    if (i == 0) {  // tail for n % 4 != 0 (empty for BATCH=262144)
        for (int j = n4 << 2; j < n; j++) out[j] = eval_one(t[j], x[j], cf);
    }
}

extern "C" void kernel_launch(void* const* d_in, const int* in_sizes, int n_in,
                              void* d_out, int out_size) {
    const float* t     = (const float*)d_in[0];
    const float* x     = (const float*)d_in[1];
    const float* ph_x1 = (const float*)d_in[2];
    const float* ph_x2 = (const float*)d_in[3];
    const float* ph_t1 = (const float*)d_in[4];
    const float* ph_t2 = (const float*)d_in[5];
    float* out = (float*)d_out;
    int n = in_sizes[0];

    qpinn_setup<<<1, 32>>>(ph_x1, ph_x2, ph_t1, ph_t2);

    int n4 = n >> 2;
    int blocks = (n4 + 255) / 256;
    if (blocks < 1) blocks = 1;
    qpinn_main<<<blocks, 256>>>(t, x, out, n);
}

// round 4
// speedup vs baseline: 2.0250x; 2.0250x over previous
#include <cuda_runtime.h>
#include <cuda_bf16.h>

// Single fused kernel. Per block:
//   1. every thread issues its input loads (DRAM latency starts ticking)
//   2. lanes 0..13 compute sincos(p/2) for the 14 phases -> smem
//   3. thread 0 symbolically propagates the QSP chains (fully unrolled,
//      register-only) into 28 closed-form coefficients:
//        A(z) = P3(z) + sqrt(1-z^2) * Q2(z)   per block (x, t)
//   4. all threads evaluate  out = Re[A_x(x) * A_t(t)]  (1/16 folded in)
//
// Coefficient layout in smem (28 floats):
//   [0..3] exr [4..7] exi [8..10] fxr [11..13] fxi
//   [14..17] etr [18..21] eti [22..24] ftr [25..27] fti

// Propagate v = RZ(p_{N-1}) S ... S RZ(p_0) (1,1)^T symbolically.
// cs[k] = (cos(p_k/2), sin(p_k/2)). After d S-steps coeffs are indexed by
// s-power j (monomial z^(d-j) s^j). out[j] = v0[j] + v1[j].
// N is a compile-time constant: all loops fully unroll, state stays in regs.
template <int N>
__device__ __forceinline__ void chain_coeffs_T(const float2* cs, float2* out) {
    float2 v0[N], v1[N];
    v0[0] = make_float2(cs[0].x, -cs[0].y);
    v1[0] = make_float2(cs[0].x,  cs[0].y);
#pragma unroll
    for (int k = 1; k < N; k++) {
        float2 n0[N], n1[N];
#pragma unroll
        for (int j = 0; j <= k; j++) {
            n0[j] = make_float2(0.f, 0.f);
            n1[j] = make_float2(0.f, 0.f);
        }
#pragma unroll
        for (int j = 0; j < k; j++) {
            // z * v : same s-power j
            n0[j].x += v0[j].x; n0[j].y += v0[j].y;
            n1[j].x += v1[j].x; n1[j].y += v1[j].y;
            // i*s * (other) : s-power j+1
            n0[j + 1].x += -v1[j].y; n0[j + 1].y += v1[j].x;
            n1[j + 1].x += -v0[j].y; n1[j + 1].y += v0[j].x;
        }
        float c = cs[k].x, s = cs[k].y;
#pragma unroll
        for (int j = 0; j <= k; j++) {
            // v0 *= (c - i s); v1 *= (c + i s)
            v0[j] = make_float2(n0[j].x * c + n0[j].y * s, n0[j].y * c - n0[j].x * s);
            v1[j] = make_float2(n1[j].x * c - n1[j].y * s, n1[j].y * c + n1[j].x * s);
        }
    }
#pragma unroll
    for (int j = 0; j < N; j++)
        out[j] = make_float2(v0[j].x + v1[j].x, v0[j].y + v1[j].y);
}

// A = P(z) + s*Q(z): P cubic, Q quadratic, Horner.
__device__ __forceinline__ void eval_block(float z, float s, const float* cf,
                                           float& Ar, float& Ai) {
    float pr = fmaf(cf[3], z, cf[2]);
    pr = fmaf(pr, z, cf[1]);
    pr = fmaf(pr, z, cf[0]);
    float pi = fmaf(cf[7], z, cf[6]);
    pi = fmaf(pi, z, cf[5]);
    pi = fmaf(pi, z, cf[4]);
    float qr = fmaf(cf[10], z, cf[9]);
    qr = fmaf(qr, z, cf[8]);
    float qi = fmaf(cf[13], z, cf[12]);
    qi = fmaf(qi, z, cf[11]);
    Ar = fmaf(s, qr, pr);
    Ai = fmaf(s, qi, pi);
}

__device__ __forceinline__ float eval_one(float t, float x, const float* cf) {
    float sx = sqrtf(fmaxf(fmaf(-x, x, 1.0f), 0.0f));
    float st = sqrtf(fmaxf(fmaf(-t, t, 1.0f), 0.0f));
    float Axr, Axi, Atr, Ati;
    eval_block(x, sx, cf, Axr, Axi);
    eval_block(t, st, cf + 14, Atr, Ati);
    return fmaf(Axr, Atr, -Axi * Ati);
}

__global__ void __launch_bounds__(256)
qpinn_fused(const float* __restrict__ t, const float* __restrict__ x,
            const float* __restrict__ ph_x1, const float* __restrict__ ph_x2,
            const float* __restrict__ ph_t1, const float* __restrict__ ph_t2,
            float* __restrict__ out, int n) {
    __shared__ float2 s_cs[14];
    __shared__ float s_cf[28];

    // ---- 1. issue input loads first: prologue hides under DRAM latency ----
    int n2 = n >> 1;
    int i = blockIdx.x * blockDim.x + threadIdx.x;
    float2 tv = make_float2(0.f, 0.f), xv = make_float2(0.f, 0.f);
    if (i < n2) {
        tv = reinterpret_cast<const float2*>(t)[i];
        xv = reinterpret_cast<const float2*>(x)[i];
    }

    // ---- 2. lane-parallel sincos of the 14 phases ----
    int l = threadIdx.x;
    if (l < 14) {
        float p;
        if (l < 3)       p = ph_x1[l];
        else if (l < 7)  p = ph_x2[l - 3];
        else if (l < 10) p = ph_t1[l - 7];
        else             p = ph_t2[l - 10];
        float s, c;
        sincosf(0.5f * p, &s, &c);
        s_cs[l] = make_float2(c, s);
    }
    __syncthreads();

    // ---- 3. thread 0: symbolic chains -> closed-form coefficients ----
    if (threadIdx.x == 0) {
        float2 cs[14];
#pragma unroll
        for (int j = 0; j < 14; j++) cs[j] = s_cs[j];

        // x-block: chains at phases [0..2] (len 3) and [3..6] (len 4)
        // t-block: chains at phases [7..9] (len 3) and [10..13] (len 4)
#pragma unroll
        for (int blk = 0; blk < 2; blk++) {
            float2 e0 = make_float2(0.f, 0.f), e1 = make_float2(0.f, 0.f);
            float2 e2 = make_float2(0.f, 0.f), e3 = make_float2(0.f, 0.f);
            float2 f0 = make_float2(0.f, 0.f), f1 = make_float2(0.f, 0.f);
            float2 f2 = make_float2(0.f, 0.f);

            // degree-2 chain: o0 z^2 + o1 z s + o2 s^2
            //   = o2 + (o0-o2) z^2 + s*(o1 z)
            float2 o2c[3];
            chain_coeffs_T<3>(cs + (blk ? 7 : 0), o2c);
            e0.x += o2c[2].x;            e0.y += o2c[2].y;
            e2.x += o2c[0].x - o2c[2].x; e2.y += o2c[0].y - o2c[2].y;
            f1.x += o2c[1].x;            f1.y += o2c[1].y;

            // degree-3 chain: o0 z^3 + o1 z^2 s + o2 z s^2 + o3 s^3
            //   = o2 z + (o0-o2) z^3 + s*(o3 + (o1-o3) z^2)
            float2 o3c[4];
            chain_coeffs_T<4>(cs + (blk ? 10 : 3), o3c);
            e1.x += o3c[2].x;            e1.y += o3c[2].y;
            e3.x += o3c[0].x - o3c[2].x; e3.y += o3c[0].y - o3c[2].y;
            f0.x += o3c[3].x;            f0.y += o3c[3].y;
            f2.x += o3c[1].x - o3c[3].x; f2.y += o3c[1].y - o3c[3].y;

            float scale = (blk == 0) ? 0.0625f : 1.0f;  // fold 1/16 into x-block
            float* base = s_cf + blk * 14;
            base[0]  = e0.x * scale; base[1]  = e1.x * scale;
            base[2]  = e2.x * scale; base[3]  = e3.x * scale;
            base[4]  = e0.y * scale; base[5]  = e1.y * scale;
            base[6]  = e2.y * scale; base[7]  = e3.y * scale;
            base[8]  = f0.x * scale; base[9]  = f1.x * scale; base[10] = f2.x * scale;
            base[11] = f0.y * scale; base[12] = f1.y * scale; base[13] = f2.y * scale;
        }
    }
    __syncthreads();

    // ---- 4. evaluate (coefficients broadcast from smem -> regs) ----
    float cf[28];
#pragma unroll
    for (int j = 0; j < 28; j++) cf[j] = s_cf[j];

    if (i < n2) {
        float2 o;
        o.x = eval_one(tv.x, xv.x, cf);
        o.y = eval_one(tv.y, xv.y, cf);
        reinterpret_cast<float2*>(out)[i] = o;
    }
    // tail for odd n (empty for BATCH=262144)
    if (i == 0 && (n & 1)) out[n - 1] = eval_one(t[n - 1], x[n - 1], cf);
}

extern "C" void kernel_launch(void* const* d_in, const int* in_sizes, int n_in,
                              void* d_out, int out_size) {
    const float* t     = (const float*)d_in[0];
    const float* x     = (const float*)d_in[1];
    const float* ph_x1 = (const float*)d_in[2];
    const float* ph_x2 = (const float*)d_in[3];
    const float* ph_t1 = (const float*)d_in[4];
    const float* ph_t2 = (const float*)d_in[5];
    float* out = (float*)d_out;
    int n = in_sizes[0];

    int n2 = n >> 1;
    int blocks = (n2 + 255) / 256;
    if (blocks < 1) blocks = 1;
    qpinn_fused<<<blocks, 256>>>(t, x, ph_x1, ph_x2, ph_t1, ph_t2, out, n);
}